// round 4
// baseline (speedup 1.0000x reference)
#include <cuda_runtime.h>
#include <cstdint>

// Problem dims (fixed for this problem instance)
#define B_BATCH 16
#define L_SEQ   2048
#define D_DIM   256
#define K_CODES 1024
#define M_ROWS  (B_BATCH * L_SEQ)   // 32768

// GEMM-argmin tiling
#define BM 128
#define BN 128
#define BK 32
#define TM 8
#define TN 8
#define THREADS 256
#define AS_STRIDE (BM + 4)   // 132 — padded, transposed A: As[k][row]
#define BS_STRIDE (BN + 4)   // 132 — padded, transposed B: Bs[k][code]

// Scratch (device globals — no allocations allowed)
__device__ int   g_idx[M_ROWS];
__device__ float g_cbsq[K_CODES];
__device__ float g_ploss[M_ROWS / 8];
__device__ float g_pden[M_ROWS / 8];

// ---------------------------------------------------------------------------
// Packed fp32x2 helpers (Blackwell FFMA2 path — only reachable via PTX)
// ---------------------------------------------------------------------------
__device__ __forceinline__ void fma2(unsigned long long& d,
                                     unsigned long long a,
                                     unsigned long long b) {
    asm("fma.rn.f32x2 %0, %1, %2, %0;" : "+l"(d) : "l"(a), "l"(b));
}

__device__ __forceinline__ unsigned long long dupf(float x) {
    unsigned long long r;
    unsigned int u = __float_as_uint(x);
    asm("mov.b64 %0, {%1, %1};" : "=l"(r) : "r"(u));
    return r;
}

__device__ __forceinline__ float lo32(unsigned long long v) {
    return __uint_as_float((unsigned int)(v & 0xffffffffull));
}
__device__ __forceinline__ float hi32(unsigned long long v) {
    return __uint_as_float((unsigned int)(v >> 32));
}

// ---------------------------------------------------------------------------
// Kernel 0: per-code squared norms  cb_sq[k] = sum_d w[k][d]^2
// ---------------------------------------------------------------------------
__global__ void cbsq_kernel(const float* __restrict__ cb) {
    int warp = (blockIdx.x * blockDim.x + threadIdx.x) >> 5;
    int lane = threadIdx.x & 31;
    if (warp >= K_CODES) return;
    const float* row = cb + (size_t)warp * D_DIM;
    float s = 0.f;
#pragma unroll
    for (int i = 0; i < D_DIM / 32; i++) {
        float v = row[lane + i * 32];
        s += v * v;
    }
#pragma unroll
    for (int o = 16; o > 0; o >>= 1) s += __shfl_down_sync(0xffffffffu, s, o);
    if (lane == 0) g_cbsq[warp] = s;
}

// ---------------------------------------------------------------------------
// Kernel 1: fused GEMM + argmin.
// Block = 128 feature rows vs all 1024 codes. A (128x256) staged fully in smem
// (transposed); B streamed in 32x128 transposed tiles. 8x8 micro-tile per
// thread as 4x8 packed f32x2 accumulators (rows paired).
// ---------------------------------------------------------------------------
extern __shared__ float sm_dyn[];

__global__ void __launch_bounds__(THREADS, 1)
argmin_kernel(const float* __restrict__ feat, const float* __restrict__ cb) {
    float* As = sm_dyn;                               // [D_DIM][AS_STRIDE]
    float* Bs = As + D_DIM * AS_STRIDE;               // [BK][BS_STRIDE]
    float* Cs = Bs + BK * BS_STRIDE;                  // [K_CODES] cb_sq copy

    const int tid = threadIdx.x;
    const int tx = tid & 15;        // code group
    const int ty = tid >> 4;        // row group
    const int rowBase = blockIdx.x * BM;

    // cb_sq -> smem
#pragma unroll
    for (int i = 0; i < K_CODES / THREADS; i++)
        Cs[tid + i * THREADS] = g_cbsq[tid + i * THREADS];

    // Fill A transposed: As[d][row]. Mapping chosen for conflict-free STS
    // (consecutive lanes -> consecutive rows); global reads are 16B-granular
    // scattered, fine (feature block is only 128KB).
#pragma unroll
    for (int it = 0; it < (BM * D_DIM / 4) / THREADS; it++) {
        int p = tid + it * THREADS;
        int row = p & (BM - 1);
        int d4 = p >> 7;                               // p / BM
        const float4 v = *reinterpret_cast<const float4*>(
            feat + (size_t)(rowBase + row) * D_DIM + d4 * 4);
        As[(d4 * 4 + 0) * AS_STRIDE + row] = v.x;
        As[(d4 * 4 + 1) * AS_STRIDE + row] = v.y;
        As[(d4 * 4 + 2) * AS_STRIDE + row] = v.z;
        As[(d4 * 4 + 3) * AS_STRIDE + row] = v.w;
    }
    __syncthreads();

    float minv[TM];
    int   mini[TM];
#pragma unroll
    for (int i = 0; i < TM; i++) { minv[i] = 3.4e38f; mini[i] = 0; }

    for (int ct = 0; ct < K_CODES / BN; ct++) {
        unsigned long long acc2[TM / 2][TN];
#pragma unroll
        for (int i = 0; i < TM / 2; i++)
#pragma unroll
            for (int j = 0; j < TN; j++) acc2[i][j] = 0ull;

        for (int kt = 0; kt < D_DIM / BK; kt++) {
            // Fill B transposed: Bs[kk][code] (conflict-free STS)
#pragma unroll
            for (int it = 0; it < (BN * BK / 4) / THREADS; it++) {
                int p = tid + it * THREADS;
                int code = p & (BN - 1);
                int kk4 = p >> 7;
                const float4 v = *reinterpret_cast<const float4*>(
                    cb + (size_t)(ct * BN + code) * D_DIM + kt * BK + kk4 * 4);
                Bs[(kk4 * 4 + 0) * BS_STRIDE + code] = v.x;
                Bs[(kk4 * 4 + 1) * BS_STRIDE + code] = v.y;
                Bs[(kk4 * 4 + 2) * BS_STRIDE + code] = v.z;
                Bs[(kk4 * 4 + 3) * BS_STRIDE + code] = v.w;
            }
            __syncthreads();

#pragma unroll 8
            for (int kk = 0; kk < BK; kk++) {
                const int k = kt * BK + kk;
                // A: 8 contiguous rows -> 4 packed row-pairs, free from 64-bit loads
                const ulonglong2* ap = reinterpret_cast<const ulonglong2*>(
                    As + k * AS_STRIDE + ty * TM);
                ulonglong2 av0 = ap[0];
                ulonglong2 av1 = ap[1];
                unsigned long long a2[4] = {av0.x, av0.y, av1.x, av1.y};

                // B: 8 scalar codes, each duplicated into a packed pair
                const float4* bp = reinterpret_cast<const float4*>(
                    Bs + kk * BS_STRIDE + tx * TN);
                float4 bv0 = bp[0];
                float4 bv1 = bp[1];
                unsigned long long b2[8];
                b2[0] = dupf(bv0.x); b2[1] = dupf(bv0.y);
                b2[2] = dupf(bv0.z); b2[3] = dupf(bv0.w);
                b2[4] = dupf(bv1.x); b2[5] = dupf(bv1.y);
                b2[6] = dupf(bv1.z); b2[7] = dupf(bv1.w);

#pragma unroll
                for (int j = 0; j < TN; j++)
#pragma unroll
                    for (int i = 0; i < TM / 2; i++)
                        fma2(acc2[i][j], a2[i], b2[j]);
            }
            __syncthreads();
        }

        // dist = cb_sq - 2*dot ; running (min, argmin) per local row
#pragma unroll
        for (int j = 0; j < TN; j++) {
            int code = ct * BN + tx * TN + j;
            float cq = Cs[code];
#pragma unroll
            for (int i2 = 0; i2 < TM / 2; i2++) {
                float d0 = cq - 2.0f * lo32(acc2[i2][j]);
                float d1 = cq - 2.0f * hi32(acc2[i2][j]);
                int r0 = 2 * i2, r1 = 2 * i2 + 1;
                if (d0 < minv[r0]) { minv[r0] = d0; mini[r0] = code; }
                if (d1 < minv[r1]) { minv[r1] = d1; mini[r1] = code; }
            }
        }
    }

    // Cross-thread reduce: 16 tx-threads share each row. Reuse As region.
    float* redv = As;                                  // [BM][16]
    int*   redi = reinterpret_cast<int*>(As + BM * 16);
#pragma unroll
    for (int i = 0; i < TM; i++) {
        redv[(ty * TM + i) * 16 + tx] = minv[i];
        redi[(ty * TM + i) * 16 + tx] = mini[i];
    }
    __syncthreads();
    if (tid < BM) {
        float bv = redv[tid * 16];
        int   bi = redi[tid * 16];
#pragma unroll
        for (int t = 1; t < 16; t++) {
            float v = redv[tid * 16 + t];
            int  ix = redi[tid * 16 + t];
            if (v < bv || (v == bv && ix < bi)) { bv = v; bi = ix; }
        }
        g_idx[rowBase + tid] = bi;
    }
}

// ---------------------------------------------------------------------------
// Kernel 2: gather codebook rows, write quantized_st = f + (q - f) exactly as
// reference, accumulate per-block masked squared-error + mask sums
// (deterministic: no atomics).
// ---------------------------------------------------------------------------
__global__ void gather_loss_kernel(const float* __restrict__ feat,
                                   const float* __restrict__ mask,
                                   const float* __restrict__ cb,
                                   float* __restrict__ outq) {
    __shared__ float sl[8];
    __shared__ float sd[8];
    const int warp = threadIdx.x >> 5;
    const int lane = threadIdx.x & 31;
    const int r = blockIdx.x * 8 + warp;

    const int idx = g_idx[r];
    const float* f = feat + (size_t)r * D_DIM;
    const float* w = cb + (size_t)idx * D_DIM;
    float* o = outq + (size_t)r * D_DIM;

    float s = 0.f;
#pragma unroll
    for (int u = 0; u < 2; u++) {
        int c = lane * 4 + u * 128;
        float4 fv = *reinterpret_cast<const float4*>(f + c);
        float4 wv = *reinterpret_cast<const float4*>(w + c);
        float4 ov;
        ov.x = fv.x + (wv.x - fv.x);
        ov.y = fv.y + (wv.y - fv.y);
        ov.z = fv.z + (wv.z - fv.z);
        ov.w = fv.w + (wv.w - fv.w);
        *reinterpret_cast<float4*>(o + c) = ov;
        float dx = fv.x - wv.x, dy = fv.y - wv.y;
        float dz = fv.z - wv.z, dw = fv.w - wv.w;
        s += dx * dx + dy * dy + dz * dz + dw * dw;
    }
#pragma unroll
    for (int of = 16; of > 0; of >>= 1) s += __shfl_down_sync(0xffffffffu, s, of);
    if (lane == 0) {
        float m = mask[r];
        sl[warp] = s * m;
        sd[warp] = m;
    }
    __syncthreads();
    if (threadIdx.x == 0) {
        float L = 0.f, Dn = 0.f;
#pragma unroll
        for (int i = 0; i < 8; i++) { L += sl[i]; Dn += sd[i]; }
        g_ploss[blockIdx.x] = L;
        g_pden[blockIdx.x] = Dn;
    }
}

// ---------------------------------------------------------------------------
// Kernel 3: reduce partials per batch, write both losses (identical forward).
// ---------------------------------------------------------------------------
__global__ void finalize_kernel(float* __restrict__ out) {
    __shared__ float sl[256];
    __shared__ float sd[256];
    const int b = blockIdx.x, t = threadIdx.x;
    const int per = (M_ROWS / 8) / B_BATCH;   // 256 partials per batch
    sl[t] = g_ploss[b * per + t];
    sd[t] = g_pden[b * per + t];
    __syncthreads();
    for (int s = 128; s > 0; s >>= 1) {
        if (t < s) { sl[t] += sl[t + s]; sd[t] += sd[t + s]; }
        __syncthreads();
    }
    if (t == 0) {
        float loss = sl[0] / sd[0];
        size_t q = (size_t)M_ROWS * D_DIM;
        out[q + b] = loss;                 // quant_loss
        out[q + B_BATCH + b] = loss;       // commit_loss (numerically identical)
    }
}

// ---------------------------------------------------------------------------
extern "C" void kernel_launch(void* const* d_in, const int* in_sizes, int n_in,
                              void* d_out, int out_size) {
    const float* feat = (const float*)d_in[0];   // [16, 2048, 256] f32
    const float* mask = (const float*)d_in[1];   // [16, 2048] f32
    const float* cb   = (const float*)d_in[2];   // [1024, 256] f32
    float* out = (float*)d_out;

    constexpr size_t SMEM =
        (size_t)(D_DIM * AS_STRIDE + BK * BS_STRIDE + K_CODES) * sizeof(float);
    cudaFuncSetAttribute(argmin_kernel,
                         cudaFuncAttributeMaxDynamicSharedMemorySize, (int)SMEM);

    cbsq_kernel<<<K_CODES / 8, 256>>>(cb);
    argmin_kernel<<<M_ROWS / BM, THREADS, SMEM>>>(feat, cb);
    gather_loss_kernel<<<M_ROWS / 8, 256>>>(feat, mask, cb, out);
    finalize_kernel<<<B_BATCH, 256>>>(out);
}